// round 9
// baseline (speedup 1.0000x reference)
#include <cuda_runtime.h>
#include <cuda_fp16.h>
#include <math.h>

#define TOK 1024
#define HDIM 2880
#define DDIM 2880
#define NEXP 8
#define GUCOLS 5760
#define ALPHA 1.702f
#define LIMIT 7.0f

__device__ __align__(16) __half g_wgu_h[(size_t)NEXP*HDIM*GUCOLS];
__device__ __align__(16) __half g_wd_h [(size_t)NEXP*DDIM*HDIM];
__device__ __align__(16) __half g_x_h  [(size_t)TOK*HDIM];
__device__ __align__(16) __half g_a_h  [(size_t)NEXP*TOK*DDIM];

__device__ __forceinline__ unsigned su32(const void* p){
    unsigned a; asm("{ .reg .u64 t; cvta.to.shared.u64 t, %1; cvt.u32.u64 %0, t; }":"=r"(a):"l"(p)); return a;
}
template<int N> __device__ __forceinline__ void cpwait(){
    asm volatile("cp.async.wait_group %0;"::"n"(N):"memory");
}
__device__ __forceinline__ void cpcommit(){
    asm volatile("cp.async.commit_group;":::"memory");
}
__device__ __forceinline__ void cpa16(unsigned d, const void* s){
    asm volatile("cp.async.cg.shared.global [%0], [%1], 16;"::"r"(d),"l"(s):"memory");
}
__device__ __forceinline__ void ldsm4(unsigned* r, unsigned a){
    asm volatile("ldmatrix.sync.aligned.m8n8.x4.shared.b16 {%0,%1,%2,%3}, [%4];"
        :"=r"(r[0]),"=r"(r[1]),"=r"(r[2]),"=r"(r[3]):"r"(a));
}
__device__ __forceinline__ void ldsm4t(unsigned* r, unsigned a){
    asm volatile("ldmatrix.sync.aligned.m8n8.x4.trans.shared.b16 {%0,%1,%2,%3}, [%4];"
        :"=r"(r[0]),"=r"(r[1]),"=r"(r[2]),"=r"(r[3]):"r"(a));
}
__device__ __forceinline__ void mma_fp(float* c, const unsigned* a, const unsigned* b){
    asm volatile("mma.sync.aligned.m16n8k16.row.col.f32.f16.f16.f32 "
        "{%0,%1,%2,%3},{%4,%5,%6,%7},{%8,%9},{%0,%1,%2,%3};"
        : "+f"(c[0]),"+f"(c[1]),"+f"(c[2]),"+f"(c[3])
        : "r"(a[0]),"r"(a[1]),"r"(a[2]),"r"(a[3]),"r"(b[0]),"r"(b[1]));
}

// -------- fused fp32 -> fp16 convert of x, wgu, wd --------
#define CVT_N1 ((long long)TOK*HDIM/4)
#define CVT_N2 ((long long)NEXP*HDIM*GUCOLS/4)
#define CVT_N3 ((long long)NEXP*DDIM*HDIM/4)

__global__ void cvt_kernel(const float4* __restrict__ x, const float4* __restrict__ wgu,
                           const float4* __restrict__ wd){
    const long long NT=CVT_N1+CVT_N2+CVT_N3;
    long long i=(long long)blockIdx.x*blockDim.x+threadIdx.x, st=(long long)gridDim.x*blockDim.x;
    for(; i<NT; i+=st){
        const float4* s; uint2* d; long long j;
        if(i<CVT_N1){ s=x; d=(uint2*)g_x_h; j=i; }
        else if(i<CVT_N1+CVT_N2){ s=wgu; d=(uint2*)g_wgu_h; j=i-CVT_N1; }
        else { s=wd; d=(uint2*)g_wd_h; j=i-CVT_N1-CVT_N2; }
        float4 f=s[j];
        uint2 v;
        v.x=(unsigned)__half_as_ushort(__float2half_rn(f.x))
           |((unsigned)__half_as_ushort(__float2half_rn(f.y))<<16);
        v.y=(unsigned)__half_as_ushort(__float2half_rn(f.z))
           |((unsigned)__half_as_ushort(__float2half_rn(f.w))<<16);
        d[j]=v;
    }
}

// ======================= GEMM1: gate_up + SwiGLU =======================
// CTA tile: 128 tokens x 128 gu-cols, K-chunk 64 (two 32-K sub-blocks).
// 256 thr, warps 2m x 4n (64x32). Stage 32KB, 3 stages, 2 CTAs/SM.
#define S1_STAGE 32768

__global__ __launch_bounds__(256,2)
void gemm1_kernel(const float* __restrict__ rw, const float* __restrict__ bgu)
{
    extern __shared__ __align__(16) char dsm[];
    __shared__ float sBias[128];
    __shared__ float sRw[128];
    const int tid=threadIdx.x, lane=tid&31, w=tid>>5;
    const int e=blockIdx.z, m0=blockIdx.y*128, c0=blockIdx.x*128, dbase=blockIdx.x*64;
    const unsigned db=su32(dsm);
    if(tid<128){
        sBias[tid]=bgu[(size_t)e*GUCOLS+c0+tid];
        sRw[tid]=rw[(size_t)(m0+tid)*NEXP+e];
    }

    const __half* xh = g_x_h + (size_t)m0*HDIM;
    const __half* wh = g_wgu_h + (size_t)e*HDIM*GUCOLS + c0;

    const int ar=tid>>2, ac=tid&3;
    const int br=tid>>4, bc=tid&15;
    const unsigned a_off = (unsigned)ar*64 + (unsigned)((ac ^ ((ar>>1)&3))*16);
    const unsigned b_off = (unsigned)br*256 + (unsigned)((bc ^ (br&7))*16);

    const int NCH=HDIM/64; // 45
    auto LOAD=[&](int kc){
        if(kc<NCH){
            const unsigned st=db+(unsigned)(kc%3)*S1_STAGE;
            const int k0=kc*64;
            cpa16(st+a_off,       xh+(size_t)ar*HDIM+k0+ac*8);
            cpa16(st+4096+a_off,  xh+(size_t)(ar+64)*HDIM+k0+ac*8);
            cpa16(st+8192+a_off,  xh+(size_t)ar*HDIM+k0+32+ac*8);
            cpa16(st+12288+a_off, xh+(size_t)(ar+64)*HDIM+k0+32+ac*8);
            cpa16(st+16384+b_off, wh+(size_t)(k0+br)*GUCOLS+bc*8);
            cpa16(st+20480+b_off, wh+(size_t)(k0+br+16)*GUCOLS+bc*8);
            cpa16(st+24576+b_off, wh+(size_t)(k0+32+br)*GUCOLS+bc*8);
            cpa16(st+28672+b_off, wh+(size_t)(k0+32+br+16)*GUCOLS+bc*8);
        }
        cpcommit();
    };

    const int mw=(w&1)*64, nw=(w>>1)*32;
    float C[4][4][4];
    #pragma unroll
    for(int i=0;i<4;i++)
        #pragma unroll
        for(int j=0;j<4;j++)
            #pragma unroll
            for(int q=0;q<4;q++) C[i][j][q]=0.f;

    const int rl=lane&15;
    const unsigned aswz=((rl>>1)&3);
    const unsigned bswz=(lane&7);

    LOAD(0); LOAD(1);
    for(int kc=0;kc<NCH;kc++){
        if(kc==NCH-1) cpwait<0>(); else cpwait<1>();
        __syncthreads();
        LOAD(kc+2);
        const unsigned ab=db+(unsigned)(kc%3)*S1_STAGE;
        #pragma unroll
        for(int h=0;h<2;h++){
            const unsigned ah=ab+h*8192;
            const unsigned bh=ab+16384+h*8192;
            #pragma unroll
            for(int ks=0;ks<2;ks++){
                unsigned a[4][4],b[4][2];
                const unsigned boff=bh+(unsigned)(ks*16+rl)*256;
                #pragma unroll
                for(int p=0;p<2;p++){
                    unsigned r4[4];
                    ldsm4t(r4, boff+((((nw>>3)+p*2+(lane>>4))^bswz)*16));
                    b[p*2][0]=r4[0]; b[p*2][1]=r4[1];
                    b[p*2+1][0]=r4[2]; b[p*2+1][1]=r4[3];
                }
                const unsigned aoff=ah+(unsigned)(mw+rl)*64+((((lane>>4)+ks*2)^aswz)*16);
                #pragma unroll
                for(int mt=0;mt<4;mt++) ldsm4(a[mt],aoff+mt*1024);
                #pragma unroll
                for(int mt=0;mt<4;mt++)
                    #pragma unroll
                    for(int nt=0;nt<4;nt++)
                        mma_fp(C[mt][nt],a[mt],b[nt]);
            }
        }
    }
    __syncthreads();

    // epilogue: bias + SwiGLU + rw -> sv (fp32), then convert to act fp16
    float* sv=(float*)dsm;
    const int grp=lane>>2, tq=lane&3;
    #pragma unroll
    for(int mt=0;mt<4;mt++)
        #pragma unroll
        for(int nt=0;nt<4;nt++){
            const int colL=nw+nt*8+tq*2;
            const int d=(nw>>1)+nt*4+tq;
            #pragma unroll
            for(int h=0;h<2;h++){
                const int row=mw+mt*16+grp+h*8;
                float g=C[mt][nt][2*h]  +sBias[colL];
                float u=C[mt][nt][2*h+1]+sBias[colL+1];
                g=fminf(g,LIMIT);
                u=fminf(fmaxf(u,-LIMIT),LIMIT);
                float glu=g/(1.0f+__expf(-ALPHA*g));
                sv[row*68+d]=(u+1.0f)*glu*sRw[row];
            }
        }
    __syncthreads();
    {
        const int row=tid>>1, d0=(tid&1)*32;
        __half* oh=g_a_h+((size_t)e*TOK+m0+row)*DDIM+dbase+d0;
        #pragma unroll
        for(int j=0;j<32;j+=8){
            unsigned hv[4];
            #pragma unroll
            for(int q=0;q<4;q++){
                float aa=sv[row*68+d0+j+2*q], b=sv[row*68+d0+j+2*q+1];
                hv[q]=(unsigned)__half_as_ushort(__float2half_rn(aa))
                     |((unsigned)__half_as_ushort(__float2half_rn(b))<<16);
            }
            *(uint4*)(oh+j)=make_uint4(hv[0],hv[1],hv[2],hv[3]);
        }
    }
}

// ======================= GEMM2: down proj + bias + expert sum =======================
// CTA tile: 128 tokens x 96 h, K-chunk 64. 256 thr, warps 4m x 2n (32x48).
// Stage 29696 (A 16K | B 2x6656 pad208), 3 stages, 2 CTAs/SM.
#define S2_BHI 16384
#define S2_BH2 6656
#define S2_STAGE 29696

__global__ __launch_bounds__(256,2)
void gemm2_kernel(const float* __restrict__ rw, const float* __restrict__ bd,
                  float* __restrict__ out)
{
    extern __shared__ __align__(16) char dsm[];
    __shared__ float sRw[128*8];
    __shared__ float sBd[8*96];
    const int tid=threadIdx.x, lane=tid&31, w=tid>>5;
    const int m0=blockIdx.y*128, h0=blockIdx.x*96;
    const unsigned db=su32(dsm);
    for(int i=tid;i<1024;i+=256) sRw[i]=rw[(size_t)(m0+(i>>3))*NEXP+(i&7)];
    for(int i=tid;i<768;i+=256) sBd[i]=bd[(size_t)(i/96)*HDIM+h0+(i%96)];

    const int ar=tid>>2, ac=tid&3;
    const unsigned a_off = (unsigned)ar*64 + (unsigned)((ac ^ ((ar>>1)&3))*16);

    const int NCH=NEXP*45; // 360
    auto LOAD=[&](int kc){
        if(kc<NCH){
            const int e=kc/45, kl=(kc-e*45)*64;
            const unsigned st=db+(unsigned)(kc%3)*S2_STAGE;
            const __half* ah=g_a_h+((size_t)e*TOK+m0)*DDIM+kl;
            cpa16(st+a_off,       ah+(size_t)ar*DDIM+ac*8);
            cpa16(st+4096+a_off,  ah+(size_t)(ar+64)*DDIM+ac*8);
            cpa16(st+8192+a_off,  ah+(size_t)ar*DDIM+32+ac*8);
            cpa16(st+12288+a_off, ah+(size_t)(ar+64)*DDIM+32+ac*8);
            const __half* bh=g_wd_h+((size_t)e*DDIM+kl)*HDIM+h0;
            #pragma unroll
            for(int i=0;i<3;i++){
                int ch=tid+256*i;       // 0..767
                int half=ch/384, rem=ch-half*384;
                int r=rem/12, c=rem-r*12;
                cpa16(st+S2_BHI+half*S2_BH2+r*208+c*16,
                      bh+(size_t)(half*32+r)*HDIM+c*8);
            }
        }
        cpcommit();
    };

    const int mw=(w&3)*32, nw=(w>>2)*48;
    float C[2][6][4];
    #pragma unroll
    for(int i=0;i<2;i++)
        #pragma unroll
        for(int j=0;j<6;j++)
            #pragma unroll
            for(int q=0;q<4;q++) C[i][j][q]=0.f;

    const int rl=lane&15;
    const unsigned aswz=((rl>>1)&3);

    LOAD(0); LOAD(1);
    for(int kc=0;kc<NCH;kc++){
        if(kc==NCH-1) cpwait<0>(); else cpwait<1>();
        __syncthreads();
        LOAD(kc+2);
        const unsigned ab=db+(unsigned)(kc%3)*S2_STAGE;
        #pragma unroll
        for(int h=0;h<2;h++){
            const unsigned ah=ab+h*8192;
            const unsigned bbh=ab+S2_BHI+h*S2_BH2;
            #pragma unroll
            for(int ks=0;ks<2;ks++){
                unsigned a[2][4],b[6][2];
                const unsigned bbase=bbh+(unsigned)(ks*16+rl)*208;
                #pragma unroll
                for(int p=0;p<3;p++){
                    unsigned r4[4];
                    ldsm4t(r4, bbase+(unsigned)(nw+p*16+(lane>>4)*8)*2);
                    b[p*2][0]=r4[0]; b[p*2][1]=r4[1];
                    b[p*2+1][0]=r4[2]; b[p*2+1][1]=r4[3];
                }
                const unsigned aoff=ah+(unsigned)(mw+rl)*64+((((lane>>4)+ks*2)^aswz)*16);
                #pragma unroll
                for(int mt=0;mt<2;mt++) ldsm4(a[mt],aoff+mt*1024);
                #pragma unroll
                for(int mt=0;mt<2;mt++)
                    #pragma unroll
                    for(int nt=0;nt<6;nt++)
                        mma_fp(C[mt][nt],a[mt],b[nt]);
            }
        }
    }

    // epilogue: + sum_e rw*bd (smem), write fp32 out
    const int grp=lane>>2, tq=lane&3;
    #pragma unroll
    for(int nt=0;nt<6;nt++){
        const int colL=nw+nt*8+tq*2;
        const int col=h0+colL;
        #pragma unroll
        for(int mt=0;mt<2;mt++)
            #pragma unroll
            for(int h=0;h<2;h++){
                const int row=mw+mt*16+grp+h*8;
                float v0=C[mt][nt][2*h], v1=C[mt][nt][2*h+1];
                #pragma unroll
                for(int e2=0;e2<NEXP;e2++){
                    float r=sRw[row*8+e2];
                    v0=fmaf(r,sBd[e2*96+colL],v0);
                    v1=fmaf(r,sBd[e2*96+colL+1],v1);
                }
                float2 t; t.x=v0; t.y=v1;
                *(float2*)(out+(size_t)(m0+row)*HDIM+col)=t;
            }
    }
}

extern "C" void kernel_launch(void* const* d_in, const int* in_sizes, int n_in,
                              void* d_out, int out_size)
{
    const float* x  =(const float*)d_in[0];
    const float* rw =(const float*)d_in[1];
    const float* wgu=(const float*)d_in[2];
    const float* bgu=(const float*)d_in[3];
    const float* wd =(const float*)d_in[4];
    const float* bd =(const float*)d_in[5];
    float* out=(float*)d_out;

    cudaFuncSetAttribute(gemm1_kernel, cudaFuncAttributeMaxDynamicSharedMemorySize, 3*S1_STAGE);
    cudaFuncSetAttribute(gemm2_kernel, cudaFuncAttributeMaxDynamicSharedMemorySize, 3*S2_STAGE);

    cvt_kernel<<<2368,256>>>((const float4*)x,(const float4*)wgu,(const float4*)wd);
    gemm1_kernel<<<dim3(45,8,NEXP),256,3*S1_STAGE>>>(rw,bgu);
    gemm2_kernel<<<dim3(30,8),256,3*S2_STAGE>>>(rw,bd,out);
}

// round 10
// speedup vs baseline: 1.5278x; 1.5278x over previous
#include <cuda_runtime.h>
#include <cuda_fp16.h>
#include <math.h>

#define TOK 1024
#define HDIM 2880
#define DDIM 2880
#define NEXP 8
#define GUCOLS 5760
#define ALPHA 1.702f
#define LIMIT 7.0f

__device__ __align__(16) __half g_wgu_h[(size_t)NEXP*HDIM*GUCOLS];
__device__ __align__(16) __half g_wd_h [(size_t)NEXP*DDIM*HDIM];
__device__ __align__(16) __half g_x_h  [(size_t)TOK*HDIM];
__device__ __align__(16) __half g_a_h  [(size_t)NEXP*TOK*DDIM];

__device__ __forceinline__ unsigned su32(const void* p){
    unsigned a; asm("{ .reg .u64 t; cvta.to.shared.u64 t, %1; cvt.u32.u64 %0, t; }":"=r"(a):"l"(p)); return a;
}
template<int N> __device__ __forceinline__ void cpwait(){
    asm volatile("cp.async.wait_group %0;"::"n"(N):"memory");
}
__device__ __forceinline__ void cpcommit(){
    asm volatile("cp.async.commit_group;":::"memory");
}
__device__ __forceinline__ void cpa16(unsigned d, const void* s){
    asm volatile("cp.async.cg.shared.global [%0], [%1], 16;"::"r"(d),"l"(s):"memory");
}
__device__ __forceinline__ void ldsm4(unsigned* r, unsigned a){
    asm volatile("ldmatrix.sync.aligned.m8n8.x4.shared.b16 {%0,%1,%2,%3}, [%4];"
        :"=r"(r[0]),"=r"(r[1]),"=r"(r[2]),"=r"(r[3]):"r"(a));
}
__device__ __forceinline__ void ldsm2t(unsigned* r, unsigned a){
    asm volatile("ldmatrix.sync.aligned.m8n8.x2.trans.shared.b16 {%0,%1}, [%2];"
        :"=r"(r[0]),"=r"(r[1]):"r"(a));
}
__device__ __forceinline__ void mma_fp(float* c, const unsigned* a, const unsigned* b){
    asm volatile("mma.sync.aligned.m16n8k16.row.col.f32.f16.f16.f32 "
        "{%0,%1,%2,%3},{%4,%5,%6,%7},{%8,%9},{%0,%1,%2,%3};"
        : "+f"(c[0]),"+f"(c[1]),"+f"(c[2]),"+f"(c[3])
        : "r"(a[0]),"r"(a[1]),"r"(a[2]),"r"(a[3]),"r"(b[0]),"r"(b[1]));
}

// -------- fused fp32 -> fp16 convert of x, wgu, wd (single launch) --------
#define CVT_N1 ((long long)TOK*HDIM/4)
#define CVT_N2 ((long long)NEXP*HDIM*GUCOLS/4)
#define CVT_N3 ((long long)NEXP*DDIM*HDIM/4)

__global__ void cvt_kernel(const float4* __restrict__ x, const float4* __restrict__ wgu,
                           const float4* __restrict__ wd){
    const long long NT=CVT_N1+CVT_N2+CVT_N3;
    long long i=(long long)blockIdx.x*blockDim.x+threadIdx.x, st=(long long)gridDim.x*blockDim.x;
    for(; i<NT; i+=st){
        const float4* s; uint2* d; long long j;
        if(i<CVT_N1){ s=x; d=(uint2*)g_x_h; j=i; }
        else if(i<CVT_N1+CVT_N2){ s=wgu; d=(uint2*)g_wgu_h; j=i-CVT_N1; }
        else { s=wd; d=(uint2*)g_wd_h; j=i-CVT_N1-CVT_N2; }
        float4 f=s[j];
        uint2 v;
        v.x=(unsigned)__half_as_ushort(__float2half_rn(f.x))
           |((unsigned)__half_as_ushort(__float2half_rn(f.y))<<16);
        v.y=(unsigned)__half_as_ushort(__float2half_rn(f.z))
           |((unsigned)__half_as_ushort(__float2half_rn(f.w))<<16);
        d[j]=v;
    }
}

// ======================= GEMM1: gate_up + SwiGLU =======================
// CTA tile: 128 tokens x 128 gu-cols. 256 thr, warps 2m x 4n (64x32).
// Stage 16KB (A 8K | B 8K), 4 stages, 2 CTAs/SM.  (R8 configuration)
#define S1_STAGE 16384

__global__ __launch_bounds__(256,2)
void gemm1_kernel(const float* __restrict__ rw, const float* __restrict__ bgu)
{
    extern __shared__ __align__(16) char dsm[];
    __shared__ float sBias[128];
    __shared__ float sRw[128];
    const int tid=threadIdx.x, lane=tid&31, w=tid>>5;
    const int e=blockIdx.z, m0=blockIdx.y*128, c0=blockIdx.x*128, dbase=blockIdx.x*64;
    const unsigned db=su32(dsm);
    if(tid<128){
        sBias[tid]=bgu[(size_t)e*GUCOLS+c0+tid];
        sRw[tid]=rw[(size_t)(m0+tid)*NEXP+e];
    }

    const __half* xh = g_x_h + (size_t)m0*HDIM;
    const __half* wh = g_wgu_h + (size_t)e*HDIM*GUCOLS + c0;

    const int ar=tid>>2, ac=tid&3;
    const int br=tid>>4, bc=tid&15;
    const unsigned a_off = (unsigned)ar*64 + (unsigned)((ac ^ ((ar>>1)&3))*16);
    const unsigned b_off = (unsigned)br*256 + (unsigned)((bc ^ (br&7))*16);

    const int NCH=HDIM/32; // 90
    auto LOAD=[&](int kc){
        if(kc<NCH){
            const unsigned st=db+(unsigned)(kc&3)*S1_STAGE;
            const int k0=kc*32;
            cpa16(st+a_off,       xh+(size_t)ar*HDIM+k0+ac*8);
            cpa16(st+4096+a_off,  xh+(size_t)(ar+64)*HDIM+k0+ac*8);
            cpa16(st+8192+b_off,  wh+(size_t)(k0+br)*GUCOLS+bc*8);
            cpa16(st+12288+b_off, wh+(size_t)(k0+br+16)*GUCOLS+bc*8);
        }
        cpcommit();
    };

    const int mw=(w&1)*64, nw=(w>>1)*32;
    float C[4][4][4];
    #pragma unroll
    for(int i=0;i<4;i++)
        #pragma unroll
        for(int j=0;j<4;j++)
            #pragma unroll
            for(int q=0;q<4;q++) C[i][j][q]=0.f;

    const int rl=lane&15;
    const unsigned aswz=((rl>>1)&3);
    const unsigned bswz=(lane&7);

    LOAD(0); LOAD(1); LOAD(2);
    for(int kc=0;kc<NCH;kc++){
        if(kc==NCH-1) cpwait<0>(); else cpwait<2>();
        __syncthreads();
        LOAD(kc+3);
        const unsigned ab=db+(unsigned)(kc&3)*S1_STAGE;
        const unsigned bb=ab+8192;
        #pragma unroll
        for(int ks=0;ks<2;ks++){
            unsigned a[4][4],b_h[4][2];
            const unsigned boff=bb+(unsigned)(ks*16+rl)*256;
            #pragma unroll
            for(int nt=0;nt<4;nt++)
                ldsm2t(b_h[nt],boff+((((nw>>3)+nt)^bswz)*16));
            const unsigned aoff=ab+(unsigned)(mw+rl)*64+((((lane>>4)+ks*2)^aswz)*16);
            #pragma unroll
            for(int mt=0;mt<4;mt++) ldsm4(a[mt],aoff+mt*1024);
            #pragma unroll
            for(int mt=0;mt<4;mt++)
                #pragma unroll
                for(int nt=0;nt<4;nt++)
                    mma_fp(C[mt][nt],a[mt],b_h[nt]);
        }
    }
    __syncthreads();

    // epilogue: bias + SwiGLU + rw -> sv (fp32), then convert to act fp16
    float* sv=(float*)dsm;
    const int grp=lane>>2, tq=lane&3;
    #pragma unroll
    for(int mt=0;mt<4;mt++)
        #pragma unroll
        for(int nt=0;nt<4;nt++){
            const int colL=nw+nt*8+tq*2;
            const int d=(nw>>1)+nt*4+tq;
            #pragma unroll
            for(int h=0;h<2;h++){
                const int row=mw+mt*16+grp+h*8;
                float g=C[mt][nt][2*h]  +sBias[colL];
                float u=C[mt][nt][2*h+1]+sBias[colL+1];
                g=fminf(g,LIMIT);
                u=fminf(fmaxf(u,-LIMIT),LIMIT);
                float glu=g/(1.0f+__expf(-ALPHA*g));
                sv[row*68+d]=(u+1.0f)*glu*sRw[row];
            }
        }
    __syncthreads();
    {
        const int row=tid>>1, d0=(tid&1)*32;
        __half* oh=g_a_h+((size_t)e*TOK+m0+row)*DDIM+dbase+d0;
        #pragma unroll
        for(int j=0;j<32;j+=8){
            unsigned hv[4];
            #pragma unroll
            for(int q=0;q<4;q++){
                float aa=sv[row*68+d0+j+2*q], b=sv[row*68+d0+j+2*q+1];
                hv[q]=(unsigned)__half_as_ushort(__float2half_rn(aa))
                     |((unsigned)__half_as_ushort(__float2half_rn(b))<<16);
            }
            *(uint4*)(oh+j)=make_uint4(hv[0],hv[1],hv[2],hv[3]);
        }
    }
}

// ======================= GEMM2: down proj + bias + expert sum =======================
// CTA tile: 128 tokens x 96 h. 256 thr, warps 4m x 2n (32x48). K = 8*2880.
// Stage 14848 (A 8K | B 6656 pad208), 4 stages, 2 CTAs/SM.  (R8 configuration)
#define S2_BHI 8192
#define S2_STAGE 14848

__global__ __launch_bounds__(256,2)
void gemm2_kernel(const float* __restrict__ rw, const float* __restrict__ bd,
                  float* __restrict__ out)
{
    extern __shared__ __align__(16) char dsm[];
    __shared__ float sRw[128*8];
    __shared__ float sBd[8*96];
    const int tid=threadIdx.x, lane=tid&31, w=tid>>5;
    const int m0=blockIdx.y*128, h0=blockIdx.x*96;
    const unsigned db=su32(dsm);
    for(int i=tid;i<1024;i+=256) sRw[i]=rw[(size_t)(m0+(i>>3))*NEXP+(i&7)];
    for(int i=tid;i<768;i+=256) sBd[i]=bd[(size_t)(i/96)*HDIM+h0+(i%96)];

    const int ar=tid>>2, ac=tid&3;
    const unsigned a_off = (unsigned)ar*64 + (unsigned)((ac ^ ((ar>>1)&3))*16);

    const int NCH=NEXP*90; // 720
    auto LOAD=[&](int kc){
        if(kc<NCH){
            const int e=kc/90, kl=(kc-e*90)*32;
            const unsigned st=db+(unsigned)(kc&3)*S2_STAGE;
            const __half* ah=g_a_h+((size_t)e*TOK+m0)*DDIM+kl;
            cpa16(st+a_off,       ah+(size_t)ar*DDIM+ac*8);
            cpa16(st+4096+a_off,  ah+(size_t)(ar+64)*DDIM+ac*8);
            const __half* bh=g_wd_h+((size_t)e*DDIM+kl)*HDIM+h0;
            #pragma unroll
            for(int i=0;i<2;i++){
                int ch=tid+256*i;
                if(ch<384){
                    int r=ch/12, c=ch-r*12;
                    cpa16(st+S2_BHI+r*208+c*16, bh+(size_t)r*HDIM+c*8);
                }
            }
        }
        cpcommit();
    };

    const int mw=(w&3)*32, nw=(w>>2)*48;
    float C[2][6][4];
    #pragma unroll
    for(int i=0;i<2;i++)
        #pragma unroll
        for(int j=0;j<6;j++)
            #pragma unroll
            for(int q=0;q<4;q++) C[i][j][q]=0.f;

    const int rl=lane&15;
    const unsigned aswz=((rl>>1)&3);

    LOAD(0); LOAD(1); LOAD(2);
    for(int kc=0;kc<NCH;kc++){
        if(kc==NCH-1) cpwait<0>(); else cpwait<2>();
        __syncthreads();
        LOAD(kc+3);
        const unsigned ab=db+(unsigned)(kc&3)*S2_STAGE;
        #pragma unroll
        for(int ks=0;ks<2;ks++){
            unsigned a[2][4],b_h[6][2];
            const unsigned bbase=ab+S2_BHI+(unsigned)(ks*16+rl)*208;
            #pragma unroll
            for(int nt=0;nt<6;nt++)
                ldsm2t(b_h[nt],bbase+(nw+nt*8)*2);
            const unsigned aoff=ab+(unsigned)(mw+rl)*64+((((lane>>4)+ks*2)^aswz)*16);
            #pragma unroll
            for(int mt=0;mt<2;mt++) ldsm4(a[mt],aoff+mt*1024);
            #pragma unroll
            for(int mt=0;mt<2;mt++)
                #pragma unroll
                for(int nt=0;nt<6;nt++)
                    mma_fp(C[mt][nt],a[mt],b_h[nt]);
        }
    }

    // epilogue: + sum_e rw*bd (smem), write fp32 out
    const int grp=lane>>2, tq=lane&3;
    #pragma unroll
    for(int nt=0;nt<6;nt++){
        const int colL=nw+nt*8+tq*2;
        const int col=h0+colL;
        #pragma unroll
        for(int mt=0;mt<2;mt++)
            #pragma unroll
            for(int h=0;h<2;h++){
                const int row=mw+mt*16+grp+h*8;
                float v0=C[mt][nt][2*h], v1=C[mt][nt][2*h+1];
                #pragma unroll
                for(int e2=0;e2<NEXP;e2++){
                    float r=sRw[row*8+e2];
                    v0=fmaf(r,sBd[e2*96+colL],v0);
                    v1=fmaf(r,sBd[e2*96+colL+1],v1);
                }
                float2 t; t.x=v0; t.y=v1;
                *(float2*)(out+(size_t)(m0+row)*HDIM+col)=t;
            }
    }
}

extern "C" void kernel_launch(void* const* d_in, const int* in_sizes, int n_in,
                              void* d_out, int out_size)
{
    const float* x  =(const float*)d_in[0];
    const float* rw =(const float*)d_in[1];
    const float* wgu=(const float*)d_in[2];
    const float* bgu=(const float*)d_in[3];
    const float* wd =(const float*)d_in[4];
    const float* bd =(const float*)d_in[5];
    float* out=(float*)d_out;

    cudaFuncSetAttribute(gemm1_kernel, cudaFuncAttributeMaxDynamicSharedMemorySize, 4*S1_STAGE);
    cudaFuncSetAttribute(gemm2_kernel, cudaFuncAttributeMaxDynamicSharedMemorySize, 4*S2_STAGE);

    cvt_kernel<<<2368,256>>>((const float4*)x,(const float4*)wgu,(const float4*)wd);
    gemm1_kernel<<<dim3(45,8,NEXP),256,4*S1_STAGE>>>(rw,bgu);
    gemm2_kernel<<<dim3(30,8),256,4*S2_STAGE>>>(rw,bd,out);
}

// round 11
// speedup vs baseline: 1.6025x; 1.0489x over previous
#include <cuda_runtime.h>
#include <cuda_fp16.h>
#include <math.h>

#define TOK 1024
#define HDIM 2880
#define DDIM 2880
#define NEXP 8
#define GUCOLS 5760
#define ALPHA 1.702f
#define LIMIT 7.0f

__device__ __align__(16) __half g_wgu_h[(size_t)NEXP*HDIM*GUCOLS];
__device__ __align__(16) __half g_wd_h [(size_t)NEXP*DDIM*HDIM];
__device__ __align__(16) __half g_x_h  [(size_t)TOK*HDIM];
__device__ __align__(16) __half g_a_h  [(size_t)NEXP*TOK*DDIM];

__device__ __forceinline__ unsigned su32(const void* p){
    unsigned a; asm("{ .reg .u64 t; cvta.to.shared.u64 t, %1; cvt.u32.u64 %0, t; }":"=r"(a):"l"(p)); return a;
}
template<int N> __device__ __forceinline__ void cpwait(){
    asm volatile("cp.async.wait_group %0;"::"n"(N):"memory");
}
__device__ __forceinline__ void cpcommit(){
    asm volatile("cp.async.commit_group;":::"memory");
}
__device__ __forceinline__ void cpa16(unsigned d, const void* s){
    asm volatile("cp.async.cg.shared.global [%0], [%1], 16;"::"r"(d),"l"(s):"memory");
}
__device__ __forceinline__ void ldsm4(unsigned* r, unsigned a){
    asm volatile("ldmatrix.sync.aligned.m8n8.x4.shared.b16 {%0,%1,%2,%3}, [%4];"
        :"=r"(r[0]),"=r"(r[1]),"=r"(r[2]),"=r"(r[3]):"r"(a));
}
__device__ __forceinline__ void ldsm2t(unsigned* r, unsigned a){
    asm volatile("ldmatrix.sync.aligned.m8n8.x2.trans.shared.b16 {%0,%1}, [%2];"
        :"=r"(r[0]),"=r"(r[1]):"r"(a));
}
__device__ __forceinline__ void mma_fp(float* c, const unsigned* a, const unsigned* b){
    asm volatile("mma.sync.aligned.m16n8k16.row.col.f32.f16.f16.f32 "
        "{%0,%1,%2,%3},{%4,%5,%6,%7},{%8,%9},{%0,%1,%2,%3};"
        : "+f"(c[0]),"+f"(c[1]),"+f"(c[2]),"+f"(c[3])
        : "r"(a[0]),"r"(a[1]),"r"(a[2]),"r"(a[3]),"r"(b[0]),"r"(b[1]));
}

// -------- fused fp32 -> fp16 convert of x, wgu, wd (single launch) --------
#define CVT_N1 ((long long)TOK*HDIM/4)
#define CVT_N2 ((long long)NEXP*HDIM*GUCOLS/4)
#define CVT_N3 ((long long)NEXP*DDIM*HDIM/4)

__global__ void cvt_kernel(const float4* __restrict__ x, const float4* __restrict__ wgu,
                           const float4* __restrict__ wd){
    const long long NT=CVT_N1+CVT_N2+CVT_N3;
    long long i=(long long)blockIdx.x*blockDim.x+threadIdx.x, st=(long long)gridDim.x*blockDim.x;
    for(; i<NT; i+=st){
        const float4* s; uint2* d; long long j;
        if(i<CVT_N1){ s=x; d=(uint2*)g_x_h; j=i; }
        else if(i<CVT_N1+CVT_N2){ s=wgu; d=(uint2*)g_wgu_h; j=i-CVT_N1; }
        else { s=wd; d=(uint2*)g_wd_h; j=i-CVT_N1-CVT_N2; }
        float4 f=s[j];
        uint2 v;
        v.x=(unsigned)__half_as_ushort(__float2half_rn(f.x))
           |((unsigned)__half_as_ushort(__float2half_rn(f.y))<<16);
        v.y=(unsigned)__half_as_ushort(__float2half_rn(f.z))
           |((unsigned)__half_as_ushort(__float2half_rn(f.w))<<16);
        d[j]=v;
    }
}

// ======================= GEMM1: gate_up + SwiGLU (R8 config, unchanged) ==========
#define S1_STAGE 16384

__global__ __launch_bounds__(256,2)
void gemm1_kernel(const float* __restrict__ rw, const float* __restrict__ bgu)
{
    extern __shared__ __align__(16) char dsm[];
    __shared__ float sBias[128];
    __shared__ float sRw[128];
    const int tid=threadIdx.x, lane=tid&31, w=tid>>5;
    const int e=blockIdx.z, m0=blockIdx.y*128, c0=blockIdx.x*128, dbase=blockIdx.x*64;
    const unsigned db=su32(dsm);
    if(tid<128){
        sBias[tid]=bgu[(size_t)e*GUCOLS+c0+tid];
        sRw[tid]=rw[(size_t)(m0+tid)*NEXP+e];
    }

    const __half* xh = g_x_h + (size_t)m0*HDIM;
    const __half* wh = g_wgu_h + (size_t)e*HDIM*GUCOLS + c0;

    const int ar=tid>>2, ac=tid&3;
    const int br=tid>>4, bc=tid&15;
    const unsigned a_off = (unsigned)ar*64 + (unsigned)((ac ^ ((ar>>1)&3))*16);
    const unsigned b_off = (unsigned)br*256 + (unsigned)((bc ^ (br&7))*16);

    const int NCH=HDIM/32; // 90
    auto LOAD=[&](int kc){
        if(kc<NCH){
            const unsigned st=db+(unsigned)(kc&3)*S1_STAGE;
            const int k0=kc*32;
            cpa16(st+a_off,       xh+(size_t)ar*HDIM+k0+ac*8);
            cpa16(st+4096+a_off,  xh+(size_t)(ar+64)*HDIM+k0+ac*8);
            cpa16(st+8192+b_off,  wh+(size_t)(k0+br)*GUCOLS+bc*8);
            cpa16(st+12288+b_off, wh+(size_t)(k0+br+16)*GUCOLS+bc*8);
        }
        cpcommit();
    };

    const int mw=(w&1)*64, nw=(w>>1)*32;
    float C[4][4][4];
    #pragma unroll
    for(int i=0;i<4;i++)
        #pragma unroll
        for(int j=0;j<4;j++)
            #pragma unroll
            for(int q=0;q<4;q++) C[i][j][q]=0.f;

    const int rl=lane&15;
    const unsigned aswz=((rl>>1)&3);
    const unsigned bswz=(lane&7);

    LOAD(0); LOAD(1); LOAD(2);
    for(int kc=0;kc<NCH;kc++){
        if(kc==NCH-1) cpwait<0>(); else cpwait<2>();
        __syncthreads();
        LOAD(kc+3);
        const unsigned ab=db+(unsigned)(kc&3)*S1_STAGE;
        const unsigned bb=ab+8192;
        #pragma unroll
        for(int ks=0;ks<2;ks++){
            unsigned a[4][4],b_h[4][2];
            const unsigned boff=bb+(unsigned)(ks*16+rl)*256;
            #pragma unroll
            for(int nt=0;nt<4;nt++)
                ldsm2t(b_h[nt],boff+((((nw>>3)+nt)^bswz)*16));
            const unsigned aoff=ab+(unsigned)(mw+rl)*64+((((lane>>4)+ks*2)^aswz)*16);
            #pragma unroll
            for(int mt=0;mt<4;mt++) ldsm4(a[mt],aoff+mt*1024);
            #pragma unroll
            for(int mt=0;mt<4;mt++)
                #pragma unroll
                for(int nt=0;nt<4;nt++)
                    mma_fp(C[mt][nt],a[mt],b_h[nt]);
        }
    }
    __syncthreads();

    // epilogue: bias + SwiGLU + rw -> sv (fp32), then convert to act fp16
    float* sv=(float*)dsm;
    const int grp=lane>>2, tq=lane&3;
    #pragma unroll
    for(int mt=0;mt<4;mt++)
        #pragma unroll
        for(int nt=0;nt<4;nt++){
            const int colL=nw+nt*8+tq*2;
            const int d=(nw>>1)+nt*4+tq;
            #pragma unroll
            for(int h=0;h<2;h++){
                const int row=mw+mt*16+grp+h*8;
                float g=C[mt][nt][2*h]  +sBias[colL];
                float u=C[mt][nt][2*h+1]+sBias[colL+1];
                g=fminf(g,LIMIT);
                u=fminf(fmaxf(u,-LIMIT),LIMIT);
                float glu=g/(1.0f+__expf(-ALPHA*g));
                sv[row*68+d]=(u+1.0f)*glu*sRw[row];
            }
        }
    __syncthreads();
    {
        const int row=tid>>1, d0=(tid&1)*32;
        __half* oh=g_a_h+((size_t)e*TOK+m0+row)*DDIM+dbase+d0;
        #pragma unroll
        for(int j=0;j<32;j+=8){
            unsigned hv[4];
            #pragma unroll
            for(int q=0;q<4;q++){
                float aa=sv[row*68+d0+j+2*q], b=sv[row*68+d0+j+2*q+1];
                hv[q]=(unsigned)__half_as_ushort(__float2half_rn(aa))
                     |((unsigned)__half_as_ushort(__float2half_rn(b))<<16);
            }
            *(uint4*)(oh+j)=make_uint4(hv[0],hv[1],hv[2],hv[3]);
        }
    }
}

// ======================= GEMM2: down proj + bias + expert sum =======================
// CTA tile: 128 tokens x 80 h (288 CTAs: wave-balanced). 256 thr, warps 4m x 2n (32x40).
// Stage 13824 (A 8K | B 32x176B), 4 stages, 2 CTAs/SM.
#define S2_BHI 8192
#define S2_STAGE 13824

__global__ __launch_bounds__(256,2)
void gemm2_kernel(const float* __restrict__ rw, const float* __restrict__ bd,
                  float* __restrict__ out)
{
    extern __shared__ __align__(16) char dsm[];
    __shared__ float sRw[128*8];
    __shared__ float sBd[8*80];
    const int tid=threadIdx.x, lane=tid&31, w=tid>>5;
    const int m0=blockIdx.y*128, h0=blockIdx.x*80;
    const unsigned db=su32(dsm);
    for(int i=tid;i<1024;i+=256) sRw[i]=rw[(size_t)(m0+(i>>3))*NEXP+(i&7)];
    for(int i=tid;i<640;i+=256) sBd[i]=bd[(size_t)(i/80)*HDIM+h0+(i%80)];

    const int ar=tid>>2, ac=tid&3;
    const unsigned a_off = (unsigned)ar*64 + (unsigned)((ac ^ ((ar>>1)&3))*16);

    const int NCH=NEXP*90; // 720
    auto LOAD=[&](int kc){
        if(kc<NCH){
            const int e=kc/90, kl=(kc-e*90)*32;
            const unsigned st=db+(unsigned)(kc&3)*S2_STAGE;
            const __half* ah=g_a_h+((size_t)e*TOK+m0)*DDIM+kl;
            cpa16(st+a_off,       ah+(size_t)ar*DDIM+ac*8);
            cpa16(st+4096+a_off,  ah+(size_t)(ar+64)*DDIM+ac*8);
            const __half* bh=g_wd_h+((size_t)e*DDIM+kl)*HDIM+h0;
            #pragma unroll
            for(int i=0;i<2;i++){
                int ch=tid+256*i;      // 0..511, need 320
                if(ch<320){
                    int r=ch/10, c=ch-r*10;
                    cpa16(st+S2_BHI+r*176+c*16, bh+(size_t)r*HDIM+c*8);
                }
            }
        }
        cpcommit();
    };

    const int mw=(w&3)*32, nw=(w>>2)*40;
    float C[2][5][4];
    #pragma unroll
    for(int i=0;i<2;i++)
        #pragma unroll
        for(int j=0;j<5;j++)
            #pragma unroll
            for(int q=0;q<4;q++) C[i][j][q]=0.f;

    const int rl=lane&15;
    const unsigned aswz=((rl>>1)&3);

    LOAD(0); LOAD(1); LOAD(2);
    for(int kc=0;kc<NCH;kc++){
        if(kc==NCH-1) cpwait<0>(); else cpwait<2>();
        __syncthreads();
        LOAD(kc+3);
        const unsigned ab=db+(unsigned)(kc&3)*S2_STAGE;
        // group both ks sub-iterations' fragment loads before MMAs
        unsigned a[2][2][4],b_h[2][5][2];
        #pragma unroll
        for(int ks=0;ks<2;ks++){
            const unsigned bbase=ab+S2_BHI+(unsigned)(ks*16+rl)*176;
            #pragma unroll
            for(int nt=0;nt<5;nt++)
                ldsm2t(b_h[ks][nt],bbase+(nw+nt*8)*2);
            const unsigned aoff=ab+(unsigned)(mw+rl)*64+((((lane>>4)+ks*2)^aswz)*16);
            #pragma unroll
            for(int mt=0;mt<2;mt++) ldsm4(a[ks][mt],aoff+mt*1024);
        }
        #pragma unroll
        for(int ks=0;ks<2;ks++)
            #pragma unroll
            for(int mt=0;mt<2;mt++)
                #pragma unroll
                for(int nt=0;nt<5;nt++)
                    mma_fp(C[mt][nt],a[ks][mt],b_h[ks][nt]);
    }

    // epilogue: + sum_e rw*bd (smem), write fp32 out
    const int grp=lane>>2, tq=lane&3;
    #pragma unroll
    for(int nt=0;nt<5;nt++){
        const int colL=nw+nt*8+tq*2;
        const int col=h0+colL;
        #pragma unroll
        for(int mt=0;mt<2;mt++)
            #pragma unroll
            for(int h=0;h<2;h++){
                const int row=mw+mt*16+grp+h*8;
                float v0=C[mt][nt][2*h], v1=C[mt][nt][2*h+1];
                #pragma unroll
                for(int e2=0;e2<NEXP;e2++){
                    float r=sRw[row*8+e2];
                    v0=fmaf(r,sBd[e2*80+colL],v0);
                    v1=fmaf(r,sBd[e2*80+colL+1],v1);
                }
                float2 t; t.x=v0; t.y=v1;
                *(float2*)(out+(size_t)(m0+row)*HDIM+col)=t;
            }
    }
}

extern "C" void kernel_launch(void* const* d_in, const int* in_sizes, int n_in,
                              void* d_out, int out_size)
{
    const float* x  =(const float*)d_in[0];
    const float* rw =(const float*)d_in[1];
    const float* wgu=(const float*)d_in[2];
    const float* bgu=(const float*)d_in[3];
    const float* wd =(const float*)d_in[4];
    const float* bd =(const float*)d_in[5];
    float* out=(float*)d_out;

    cudaFuncSetAttribute(gemm1_kernel, cudaFuncAttributeMaxDynamicSharedMemorySize, 4*S1_STAGE);
    cudaFuncSetAttribute(gemm2_kernel, cudaFuncAttributeMaxDynamicSharedMemorySize, 4*S2_STAGE);

    cvt_kernel<<<2368,256>>>((const float4*)x,(const float4*)wgu,(const float4*)wd);
    gemm1_kernel<<<dim3(45,8,NEXP),256,4*S1_STAGE>>>(rw,bgu);
    gemm2_kernel<<<dim3(36,8),256,4*S2_STAGE>>>(rw,bd,out);
}

// round 12
// speedup vs baseline: 1.6580x; 1.0346x over previous
#include <cuda_runtime.h>
#include <cuda_fp16.h>
#include <math.h>

#define TOK 1024
#define HDIM 2880
#define DDIM 2880
#define NEXP 8
#define GUCOLS 5760
#define ALPHA 1.702f
#define LIMIT 7.0f

__device__ __align__(16) __half g_wgu_h[(size_t)NEXP*HDIM*GUCOLS];
__device__ __align__(16) __half g_wd_h [(size_t)NEXP*DDIM*HDIM];
__device__ __align__(16) __half g_x_h  [(size_t)TOK*HDIM];
__device__ __align__(16) __half g_a_h  [(size_t)NEXP*TOK*DDIM];

__device__ __forceinline__ unsigned su32(const void* p){
    unsigned a; asm("{ .reg .u64 t; cvta.to.shared.u64 t, %1; cvt.u32.u64 %0, t; }":"=r"(a):"l"(p)); return a;
}
template<int N> __device__ __forceinline__ void cpwait(){
    asm volatile("cp.async.wait_group %0;"::"n"(N):"memory");
}
__device__ __forceinline__ void cpcommit(){
    asm volatile("cp.async.commit_group;":::"memory");
}
__device__ __forceinline__ void cpa16(unsigned d, const void* s){
    asm volatile("cp.async.cg.shared.global [%0], [%1], 16;"::"r"(d),"l"(s):"memory");
}
__device__ __forceinline__ void ldsm4(unsigned* r, unsigned a){
    asm volatile("ldmatrix.sync.aligned.m8n8.x4.shared.b16 {%0,%1,%2,%3}, [%4];"
        :"=r"(r[0]),"=r"(r[1]),"=r"(r[2]),"=r"(r[3]):"r"(a));
}
__device__ __forceinline__ void ldsm2t(unsigned* r, unsigned a){
    asm volatile("ldmatrix.sync.aligned.m8n8.x2.trans.shared.b16 {%0,%1}, [%2];"
        :"=r"(r[0]),"=r"(r[1]):"r"(a));
}
__device__ __forceinline__ void mma_fp(float* c, const unsigned* a, const unsigned* b){
    asm volatile("mma.sync.aligned.m16n8k16.row.col.f32.f16.f16.f32 "
        "{%0,%1,%2,%3},{%4,%5,%6,%7},{%8,%9},{%0,%1,%2,%3};"
        : "+f"(c[0]),"+f"(c[1]),"+f"(c[2]),"+f"(c[3])
        : "r"(a[0]),"r"(a[1]),"r"(a[2]),"r"(a[3]),"r"(b[0]),"r"(b[1]));
}

// -------- fused fp32 -> fp16 convert of x, wgu, wd (single launch) --------
#define CVT_N1 ((long long)TOK*HDIM/4)
#define CVT_N2 ((long long)NEXP*HDIM*GUCOLS/4)
#define CVT_N3 ((long long)NEXP*DDIM*HDIM/4)

__global__ void cvt_kernel(const float4* __restrict__ x, const float4* __restrict__ wgu,
                           const float4* __restrict__ wd){
    const long long NT=CVT_N1+CVT_N2+CVT_N3;
    long long i=(long long)blockIdx.x*blockDim.x+threadIdx.x, st=(long long)gridDim.x*blockDim.x;
    for(; i<NT; i+=st){
        const float4* s; uint2* d; long long j;
        if(i<CVT_N1){ s=x; d=(uint2*)g_x_h; j=i; }
        else if(i<CVT_N1+CVT_N2){ s=wgu; d=(uint2*)g_wgu_h; j=i-CVT_N1; }
        else { s=wd; d=(uint2*)g_wd_h; j=i-CVT_N1-CVT_N2; }
        float4 f=s[j];
        uint2 v;
        v.x=(unsigned)__half_as_ushort(__float2half_rn(f.x))
           |((unsigned)__half_as_ushort(__float2half_rn(f.y))<<16);
        v.y=(unsigned)__half_as_ushort(__float2half_rn(f.z))
           |((unsigned)__half_as_ushort(__float2half_rn(f.w))<<16);
        d[j]=v;
    }
}

// ======================= GEMM1: gate_up + SwiGLU =======================
// CTA tile: 128 tokens x 128 gu-cols. 128 thr, 4 warps (2m x 2n of 64x64).
// Stage 16KB (A 8K | B 8K), 4 stages, 2 CTAs/SM, up to 255 regs/thread.
#define S1_STAGE 16384

__global__ __launch_bounds__(128,2)
void gemm1_kernel(const float* __restrict__ rw, const float* __restrict__ bgu)
{
    extern __shared__ __align__(16) char dsm[];
    __shared__ float sBias[128];
    __shared__ float sRw[128];
    const int tid=threadIdx.x, lane=tid&31, w=tid>>5;
    const int e=blockIdx.z, m0=blockIdx.y*128, c0=blockIdx.x*128, dbase=blockIdx.x*64;
    const unsigned db=su32(dsm);
    sBias[tid]=bgu[(size_t)e*GUCOLS+c0+tid];
    sRw[tid]=rw[(size_t)(m0+tid)*NEXP+e];

    const __half* xh = g_x_h + (size_t)m0*HDIM;
    const __half* wh = g_wgu_h + (size_t)e*HDIM*GUCOLS + c0;

    // loader maps: 4 A-chunks + 4 B-chunks per thread per stage
    unsigned aoffv[4], boffv[4];
    unsigned asrc[4];   // element offset into xh row-space
    unsigned bsrc_r[4], bsrc_c[4];
    #pragma unroll
    for(int i=0;i<4;i++){
        int li=tid+128*i;                  // 0..511
        int ar=li>>2, ac=li&3;
        aoffv[i]=(unsigned)ar*64 + (unsigned)((ac ^ ((ar>>1)&3))*16);
        asrc[i]=(unsigned)ar*HDIM + ac*8;
        int br2=li>>4, bc2=li&15;
        boffv[i]=8192u + (unsigned)br2*256 + (unsigned)((bc2 ^ (br2&7))*16);
        bsrc_r[i]=(unsigned)br2; bsrc_c[i]=(unsigned)bc2*8;
    }

    const int NCH=HDIM/32; // 90
    auto LOAD=[&](int kc){
        if(kc<NCH){
            const unsigned st=db+(unsigned)(kc&3)*S1_STAGE;
            const int k0=kc*32;
            #pragma unroll
            for(int i=0;i<4;i++)
                cpa16(st+aoffv[i], xh+asrc[i]+k0);
            #pragma unroll
            for(int i=0;i<4;i++)
                cpa16(st+boffv[i], wh+(size_t)(k0+bsrc_r[i])*GUCOLS+bsrc_c[i]);
        }
        cpcommit();
    };

    const int mw=(w&1)*64, nw=(w>>1)*64;
    float C[4][8][4];
    #pragma unroll
    for(int i=0;i<4;i++)
        #pragma unroll
        for(int j=0;j<8;j++)
            #pragma unroll
            for(int q=0;q<4;q++) C[i][j][q]=0.f;

    const int rl=lane&15;
    const unsigned aswz=((rl>>1)&3);
    const unsigned bswz=(lane&7);

    LOAD(0); LOAD(1); LOAD(2);
    for(int kc=0;kc<NCH;kc++){
        if(kc==NCH-1) cpwait<0>(); else cpwait<2>();
        __syncthreads();
        LOAD(kc+3);
        const unsigned ab=db+(unsigned)(kc&3)*S1_STAGE;
        const unsigned bb=ab+8192;
        #pragma unroll
        for(int ks=0;ks<2;ks++){
            unsigned a[4][4],b_h[8][2];
            const unsigned boff=bb+(unsigned)(ks*16+rl)*256;
            #pragma unroll
            for(int nt=0;nt<8;nt++)
                ldsm2t(b_h[nt],boff+((((nw>>3)+nt)^bswz)*16));
            const unsigned aoff=ab+(unsigned)(mw+rl)*64+((((lane>>4)+ks*2)^aswz)*16);
            #pragma unroll
            for(int mt=0;mt<4;mt++) ldsm4(a[mt],aoff+mt*1024);
            #pragma unroll
            for(int mt=0;mt<4;mt++)
                #pragma unroll
                for(int nt=0;nt<8;nt++)
                    mma_fp(C[mt][nt],a[mt],b_h[nt]);
        }
    }
    __syncthreads();

    // epilogue: bias + SwiGLU + rw -> sv (fp32), then convert to act fp16
    float* sv=(float*)dsm;
    const int grp=lane>>2, tq=lane&3;
    #pragma unroll
    for(int mt=0;mt<4;mt++)
        #pragma unroll
        for(int nt=0;nt<8;nt++){
            const int colL=nw+nt*8+tq*2;
            const int d=(nw>>1)+nt*4+tq;
            #pragma unroll
            for(int h=0;h<2;h++){
                const int row=mw+mt*16+grp+h*8;
                float g=C[mt][nt][2*h]  +sBias[colL];
                float u=C[mt][nt][2*h+1]+sBias[colL+1];
                g=fminf(g,LIMIT);
                u=fminf(fmaxf(u,-LIMIT),LIMIT);
                float glu=g/(1.0f+__expf(-ALPHA*g));
                sv[row*68+d]=(u+1.0f)*glu*sRw[row];
            }
        }
    __syncthreads();
    {
        const int row=tid;
        __half* oh=g_a_h+((size_t)e*TOK+m0+row)*DDIM+dbase;
        #pragma unroll
        for(int j=0;j<64;j+=8){
            unsigned hv[4];
            #pragma unroll
            for(int q=0;q<4;q++){
                float aa=sv[row*68+j+2*q], b=sv[row*68+j+2*q+1];
                hv[q]=(unsigned)__half_as_ushort(__float2half_rn(aa))
                     |((unsigned)__half_as_ushort(__float2half_rn(b))<<16);
            }
            *(uint4*)(oh+j)=make_uint4(hv[0],hv[1],hv[2],hv[3]);
        }
    }
}

// ======================= GEMM2: down proj + bias + expert sum (R11 config) ========
// CTA tile: 128 tokens x 80 h (288 CTAs). 256 thr, warps 4m x 2n (32x40).
#define S2_BHI 8192
#define S2_STAGE 13824

__global__ __launch_bounds__(256,2)
void gemm2_kernel(const float* __restrict__ rw, const float* __restrict__ bd,
                  float* __restrict__ out)
{
    extern __shared__ __align__(16) char dsm[];
    __shared__ float sRw[128*8];
    __shared__ float sBd[8*80];
    const int tid=threadIdx.x, lane=tid&31, w=tid>>5;
    const int m0=blockIdx.y*128, h0=blockIdx.x*80;
    const unsigned db=su32(dsm);
    for(int i=tid;i<1024;i+=256) sRw[i]=rw[(size_t)(m0+(i>>3))*NEXP+(i&7)];
    for(int i=tid;i<640;i+=256) sBd[i]=bd[(size_t)(i/80)*HDIM+h0+(i%80)];

    const int ar=tid>>2, ac=tid&3;
    const unsigned a_off = (unsigned)ar*64 + (unsigned)((ac ^ ((ar>>1)&3))*16);

    const int NCH=NEXP*90; // 720
    auto LOAD=[&](int kc){
        if(kc<NCH){
            const int e=kc/90, kl=(kc-e*90)*32;
            const unsigned st=db+(unsigned)(kc&3)*S2_STAGE;
            const __half* ah=g_a_h+((size_t)e*TOK+m0)*DDIM+kl;
            cpa16(st+a_off,       ah+(size_t)ar*DDIM+ac*8);
            cpa16(st+4096+a_off,  ah+(size_t)(ar+64)*DDIM+ac*8);
            const __half* bh=g_wd_h+((size_t)e*DDIM+kl)*HDIM+h0;
            #pragma unroll
            for(int i=0;i<2;i++){
                int ch=tid+256*i;
                if(ch<320){
                    int r=ch/10, c=ch-r*10;
                    cpa16(st+S2_BHI+r*176+c*16, bh+(size_t)r*HDIM+c*8);
                }
            }
        }
        cpcommit();
    };

    const int mw=(w&3)*32, nw=(w>>2)*40;
    float C[2][5][4];
    #pragma unroll
    for(int i=0;i<2;i++)
        #pragma unroll
        for(int j=0;j<5;j++)
            #pragma unroll
            for(int q=0;q<4;q++) C[i][j][q]=0.f;

    const int rl=lane&15;
    const unsigned aswz=((rl>>1)&3);

    LOAD(0); LOAD(1); LOAD(2);
    for(int kc=0;kc<NCH;kc++){
        if(kc==NCH-1) cpwait<0>(); else cpwait<2>();
        __syncthreads();
        LOAD(kc+3);
        const unsigned ab=db+(unsigned)(kc&3)*S2_STAGE;
        unsigned a[2][2][4],b_h[2][5][2];
        #pragma unroll
        for(int ks=0;ks<2;ks++){
            const unsigned bbase=ab+S2_BHI+(unsigned)(ks*16+rl)*176;
            #pragma unroll
            for(int nt=0;nt<5;nt++)
                ldsm2t(b_h[ks][nt],bbase+(nw+nt*8)*2);
            const unsigned aoff=ab+(unsigned)(mw+rl)*64+((((lane>>4)+ks*2)^aswz)*16);
            #pragma unroll
            for(int mt=0;mt<2;mt++) ldsm4(a[ks][mt],aoff+mt*1024);
        }
        #pragma unroll
        for(int ks=0;ks<2;ks++)
            #pragma unroll
            for(int mt=0;mt<2;mt++)
                #pragma unroll
                for(int nt=0;nt<5;nt++)
                    mma_fp(C[mt][nt],a[ks][mt],b_h[ks][nt]);
    }

    // epilogue: + sum_e rw*bd (smem), write fp32 out
    const int grp=lane>>2, tq=lane&3;
    #pragma unroll
    for(int nt=0;nt<5;nt++){
        const int colL=nw+nt*8+tq*2;
        const int col=h0+colL;
        #pragma unroll
        for(int mt=0;mt<2;mt++)
            #pragma unroll
            for(int h=0;h<2;h++){
                const int row=mw+mt*16+grp+h*8;
                float v0=C[mt][nt][2*h], v1=C[mt][nt][2*h+1];
                #pragma unroll
                for(int e2=0;e2<NEXP;e2++){
                    float r=sRw[row*8+e2];
                    v0=fmaf(r,sBd[e2*80+colL],v0);
                    v1=fmaf(r,sBd[e2*80+colL+1],v1);
                }
                float2 t; t.x=v0; t.y=v1;
                *(float2*)(out+(size_t)(m0+row)*HDIM+col)=t;
            }
    }
}

extern "C" void kernel_launch(void* const* d_in, const int* in_sizes, int n_in,
                              void* d_out, int out_size)
{
    const float* x  =(const float*)d_in[0];
    const float* rw =(const float*)d_in[1];
    const float* wgu=(const float*)d_in[2];
    const float* bgu=(const float*)d_in[3];
    const float* wd =(const float*)d_in[4];
    const float* bd =(const float*)d_in[5];
    float* out=(float*)d_out;

    cudaFuncSetAttribute(gemm1_kernel, cudaFuncAttributeMaxDynamicSharedMemorySize, 4*S1_STAGE);
    cudaFuncSetAttribute(gemm2_kernel, cudaFuncAttributeMaxDynamicSharedMemorySize, 4*S2_STAGE);

    cvt_kernel<<<2368,256>>>((const float4*)x,(const float4*)wgu,(const float4*)wd);
    gemm1_kernel<<<dim3(45,8,NEXP),128,4*S1_STAGE>>>(rw,bgu);
    gemm2_kernel<<<dim3(36,8),256,4*S2_STAGE>>>(rw,bd,out);
}

// round 13
// speedup vs baseline: 1.7422x; 1.0508x over previous
#include <cuda_runtime.h>
#include <cuda_fp16.h>
#include <math.h>

#define TOK 1024
#define HDIM 2880
#define DDIM 2880
#define NEXP 8
#define GUCOLS 5760
#define ALPHA 1.702f
#define LIMIT 7.0f

__device__ __align__(16) __half g_wgu_h[(size_t)NEXP*HDIM*GUCOLS];
__device__ __align__(16) __half g_wd_h [(size_t)NEXP*DDIM*HDIM];
__device__ __align__(16) __half g_x_h  [(size_t)TOK*HDIM];
__device__ __align__(16) __half g_a_h  [(size_t)NEXP*TOK*DDIM];

__device__ __forceinline__ unsigned su32(const void* p){
    unsigned a; asm("{ .reg .u64 t; cvta.to.shared.u64 t, %1; cvt.u32.u64 %0, t; }":"=r"(a):"l"(p)); return a;
}
template<int N> __device__ __forceinline__ void cpwait(){
    asm volatile("cp.async.wait_group %0;"::"n"(N):"memory");
}
__device__ __forceinline__ void cpcommit(){
    asm volatile("cp.async.commit_group;":::"memory");
}
__device__ __forceinline__ void cpa16(unsigned d, const void* s){
    asm volatile("cp.async.cg.shared.global [%0], [%1], 16;"::"r"(d),"l"(s):"memory");
}
__device__ __forceinline__ void ldsm4(unsigned* r, unsigned a){
    asm volatile("ldmatrix.sync.aligned.m8n8.x4.shared.b16 {%0,%1,%2,%3}, [%4];"
        :"=r"(r[0]),"=r"(r[1]),"=r"(r[2]),"=r"(r[3]):"r"(a));
}
__device__ __forceinline__ void ldsm2t(unsigned* r, unsigned a){
    asm volatile("ldmatrix.sync.aligned.m8n8.x2.trans.shared.b16 {%0,%1}, [%2];"
        :"=r"(r[0]),"=r"(r[1]):"r"(a));
}
__device__ __forceinline__ void mma_fp(float* c, const unsigned* a, const unsigned* b){
    asm volatile("mma.sync.aligned.m16n8k16.row.col.f32.f16.f16.f32 "
        "{%0,%1,%2,%3},{%4,%5,%6,%7},{%8,%9},{%0,%1,%2,%3};"
        : "+f"(c[0]),"+f"(c[1]),"+f"(c[2]),"+f"(c[3])
        : "r"(a[0]),"r"(a[1]),"r"(a[2]),"r"(a[3]),"r"(b[0]),"r"(b[1]));
}

// -------- fused fp32 -> fp16 convert of x, wgu, wd (single launch) --------
#define CVT_N1 ((long long)TOK*HDIM/4)
#define CVT_N2 ((long long)NEXP*HDIM*GUCOLS/4)
#define CVT_N3 ((long long)NEXP*DDIM*HDIM/4)

__global__ void cvt_kernel(const float4* __restrict__ x, const float4* __restrict__ wgu,
                           const float4* __restrict__ wd){
    const long long NT=CVT_N1+CVT_N2+CVT_N3;
    long long i=(long long)blockIdx.x*blockDim.x+threadIdx.x, st=(long long)gridDim.x*blockDim.x;
    for(; i<NT; i+=st){
        const float4* s; uint2* d; long long j;
        if(i<CVT_N1){ s=x; d=(uint2*)g_x_h; j=i; }
        else if(i<CVT_N1+CVT_N2){ s=wgu; d=(uint2*)g_wgu_h; j=i-CVT_N1; }
        else { s=wd; d=(uint2*)g_wd_h; j=i-CVT_N1-CVT_N2; }
        float4 f=s[j];
        uint2 v;
        v.x=(unsigned)__half_as_ushort(__float2half_rn(f.x))
           |((unsigned)__half_as_ushort(__float2half_rn(f.y))<<16);
        v.y=(unsigned)__half_as_ushort(__float2half_rn(f.z))
           |((unsigned)__half_as_ushort(__float2half_rn(f.w))<<16);
        d[j]=v;
    }
}

// ======================= GEMM1: gate_up + SwiGLU (R12 config, unchanged) ==========
// CTA tile: 128 x 128. 128 thr, 4 warps (2m x 2n of 64x64). 4 stages.
#define S1_STAGE 16384

__global__ __launch_bounds__(128,2)
void gemm1_kernel(const float* __restrict__ rw, const float* __restrict__ bgu)
{
    extern __shared__ __align__(16) char dsm[];
    __shared__ float sBias[128];
    __shared__ float sRw[128];
    const int tid=threadIdx.x, lane=tid&31, w=tid>>5;
    const int e=blockIdx.z, m0=blockIdx.y*128, c0=blockIdx.x*128, dbase=blockIdx.x*64;
    const unsigned db=su32(dsm);
    sBias[tid]=bgu[(size_t)e*GUCOLS+c0+tid];
    sRw[tid]=rw[(size_t)(m0+tid)*NEXP+e];

    const __half* xh = g_x_h + (size_t)m0*HDIM;
    const __half* wh = g_wgu_h + (size_t)e*HDIM*GUCOLS + c0;

    unsigned aoffv[4], boffv[4];
    unsigned asrc[4];
    unsigned bsrc_r[4], bsrc_c[4];
    #pragma unroll
    for(int i=0;i<4;i++){
        int li=tid+128*i;
        int ar=li>>2, ac=li&3;
        aoffv[i]=(unsigned)ar*64 + (unsigned)((ac ^ ((ar>>1)&3))*16);
        asrc[i]=(unsigned)ar*HDIM + ac*8;
        int br2=li>>4, bc2=li&15;
        boffv[i]=8192u + (unsigned)br2*256 + (unsigned)((bc2 ^ (br2&7))*16);
        bsrc_r[i]=(unsigned)br2; bsrc_c[i]=(unsigned)bc2*8;
    }

    const int NCH=HDIM/32; // 90
    auto LOAD=[&](int kc){
        if(kc<NCH){
            const unsigned st=db+(unsigned)(kc&3)*S1_STAGE;
            const int k0=kc*32;
            #pragma unroll
            for(int i=0;i<4;i++)
                cpa16(st+aoffv[i], xh+asrc[i]+k0);
            #pragma unroll
            for(int i=0;i<4;i++)
                cpa16(st+boffv[i], wh+(size_t)(k0+bsrc_r[i])*GUCOLS+bsrc_c[i]);
        }
        cpcommit();
    };

    const int mw=(w&1)*64, nw=(w>>1)*64;
    float C[4][8][4];
    #pragma unroll
    for(int i=0;i<4;i++)
        #pragma unroll
        for(int j=0;j<8;j++)
            #pragma unroll
            for(int q=0;q<4;q++) C[i][j][q]=0.f;

    const int rl=lane&15;
    const unsigned aswz=((rl>>1)&3);
    const unsigned bswz=(lane&7);

    LOAD(0); LOAD(1); LOAD(2);
    for(int kc=0;kc<NCH;kc++){
        if(kc==NCH-1) cpwait<0>(); else cpwait<2>();
        __syncthreads();
        LOAD(kc+3);
        const unsigned ab=db+(unsigned)(kc&3)*S1_STAGE;
        const unsigned bb=ab+8192;
        #pragma unroll
        for(int ks=0;ks<2;ks++){
            unsigned a[4][4],b_h[8][2];
            const unsigned boff=bb+(unsigned)(ks*16+rl)*256;
            #pragma unroll
            for(int nt=0;nt<8;nt++)
                ldsm2t(b_h[nt],boff+((((nw>>3)+nt)^bswz)*16));
            const unsigned aoff=ab+(unsigned)(mw+rl)*64+((((lane>>4)+ks*2)^aswz)*16);
            #pragma unroll
            for(int mt=0;mt<4;mt++) ldsm4(a[mt],aoff+mt*1024);
            #pragma unroll
            for(int mt=0;mt<4;mt++)
                #pragma unroll
                for(int nt=0;nt<8;nt++)
                    mma_fp(C[mt][nt],a[mt],b_h[nt]);
        }
    }
    __syncthreads();

    float* sv=(float*)dsm;
    const int grp=lane>>2, tq=lane&3;
    #pragma unroll
    for(int mt=0;mt<4;mt++)
        #pragma unroll
        for(int nt=0;nt<8;nt++){
            const int colL=nw+nt*8+tq*2;
            const int d=(nw>>1)+nt*4+tq;
            #pragma unroll
            for(int h=0;h<2;h++){
                const int row=mw+mt*16+grp+h*8;
                float g=C[mt][nt][2*h]  +sBias[colL];
                float u=C[mt][nt][2*h+1]+sBias[colL+1];
                g=fminf(g,LIMIT);
                u=fminf(fmaxf(u,-LIMIT),LIMIT);
                float glu=g/(1.0f+__expf(-ALPHA*g));
                sv[row*68+d]=(u+1.0f)*glu*sRw[row];
            }
        }
    __syncthreads();
    {
        const int row=tid;
        __half* oh=g_a_h+((size_t)e*TOK+m0+row)*DDIM+dbase;
        #pragma unroll
        for(int j=0;j<64;j+=8){
            unsigned hv[4];
            #pragma unroll
            for(int q=0;q<4;q++){
                float aa=sv[row*68+j+2*q], b=sv[row*68+j+2*q+1];
                hv[q]=(unsigned)__half_as_ushort(__float2half_rn(aa))
                     |((unsigned)__half_as_ushort(__float2half_rn(b))<<16);
            }
            *(uint4*)(oh+j)=make_uint4(hv[0],hv[1],hv[2],hv[3]);
        }
    }
}

// ======================= GEMM2: down proj + bias + expert sum =======================
// CTA tile: 128 tokens x 80 h (288 CTAs). 128 thr, 4 warps (2m x 2n of 64x40).
// Stage 13824 (A 8K | B 32x176B), 4 stages, 2 CTAs/SM.
#define S2_BHI 8192
#define S2_STAGE 13824

__global__ __launch_bounds__(128,2)
void gemm2_kernel(const float* __restrict__ rw, const float* __restrict__ bd,
                  float* __restrict__ out)
{
    extern __shared__ __align__(16) char dsm[];
    __shared__ float sRw[128*8];
    __shared__ float sBd[8*80];
    const int tid=threadIdx.x, lane=tid&31, w=tid>>5;
    const int m0=blockIdx.y*128, h0=blockIdx.x*80;
    const unsigned db=su32(dsm);
    for(int i=tid;i<1024;i+=128) sRw[i]=rw[(size_t)(m0+(i>>3))*NEXP+(i&7)];
    for(int i=tid;i<640;i+=128) sBd[i]=bd[(size_t)(i/80)*HDIM+h0+(i%80)];

    unsigned aoffv[4], asrc[4];
    #pragma unroll
    for(int i=0;i<4;i++){
        int li=tid+128*i;
        int ar=li>>2, ac=li&3;
        aoffv[i]=(unsigned)ar*64 + (unsigned)((ac ^ ((ar>>1)&3))*16);
        asrc[i]=(unsigned)ar*DDIM + ac*8;
    }

    const int NCH=NEXP*90; // 720
    auto LOAD=[&](int kc){
        if(kc<NCH){
            const int e=kc/90, kl=(kc-e*90)*32;
            const unsigned st=db+(unsigned)(kc&3)*S2_STAGE;
            const __half* ah=g_a_h+((size_t)e*TOK+m0)*DDIM+kl;
            #pragma unroll
            for(int i=0;i<4;i++)
                cpa16(st+aoffv[i], ah+asrc[i]);
            const __half* bh=g_wd_h+((size_t)e*DDIM+kl)*HDIM+h0;
            #pragma unroll
            for(int i=0;i<3;i++){
                int ch=tid+128*i;      // 0..383, need 320
                if(ch<320){
                    int r=ch/10, c=ch-r*10;
                    cpa16(st+S2_BHI+r*176+c*16, bh+(size_t)r*HDIM+c*8);
                }
            }
        }
        cpcommit();
    };

    const int mw=(w&1)*64, nw=(w>>1)*40;
    float C[4][5][4];
    #pragma unroll
    for(int i=0;i<4;i++)
        #pragma unroll
        for(int j=0;j<5;j++)
            #pragma unroll
            for(int q=0;q<4;q++) C[i][j][q]=0.f;

    const int rl=lane&15;
    const unsigned aswz=((rl>>1)&3);

    LOAD(0); LOAD(1); LOAD(2);
    for(int kc=0;kc<NCH;kc++){
        if(kc==NCH-1) cpwait<0>(); else cpwait<2>();
        __syncthreads();
        LOAD(kc+3);
        const unsigned ab=db+(unsigned)(kc&3)*S2_STAGE;
        #pragma unroll
        for(int ks=0;ks<2;ks++){
            unsigned a[4][4],b_h[5][2];
            const unsigned bbase=ab+S2_BHI+(unsigned)(ks*16+rl)*176;
            #pragma unroll
            for(int nt=0;nt<5;nt++)
                ldsm2t(b_h[nt],bbase+(nw+nt*8)*2);
            const unsigned aoff=ab+(unsigned)(mw+rl)*64+((((lane>>4)+ks*2)^aswz)*16);
            #pragma unroll
            for(int mt=0;mt<4;mt++) ldsm4(a[mt],aoff+mt*1024);
            #pragma unroll
            for(int mt=0;mt<4;mt++)
                #pragma unroll
                for(int nt=0;nt<5;nt++)
                    mma_fp(C[mt][nt],a[mt],b_h[nt]);
        }
    }

    // epilogue: + sum_e rw*bd (smem), write fp32 out
    const int grp=lane>>2, tq=lane&3;
    #pragma unroll
    for(int nt=0;nt<5;nt++){
        const int colL=nw+nt*8+tq*2;
        const int col=h0+colL;
        #pragma unroll
        for(int mt=0;mt<4;mt++)
            #pragma unroll
            for(int h=0;h<2;h++){
                const int row=mw+mt*16+grp+h*8;
                float v0=C[mt][nt][2*h], v1=C[mt][nt][2*h+1];
                #pragma unroll
                for(int e2=0;e2<NEXP;e2++){
                    float r=sRw[row*8+e2];
                    v0=fmaf(r,sBd[e2*80+colL],v0);
                    v1=fmaf(r,sBd[e2*80+colL+1],v1);
                }
                float2 t; t.x=v0; t.y=v1;
                *(float2*)(out+(size_t)(m0+row)*HDIM+col)=t;
            }
    }
}

extern "C" void kernel_launch(void* const* d_in, const int* in_sizes, int n_in,
                              void* d_out, int out_size)
{
    const float* x  =(const float*)d_in[0];
    const float* rw =(const float*)d_in[1];
    const float* wgu=(const float*)d_in[2];
    const float* bgu=(const float*)d_in[3];
    const float* wd =(const float*)d_in[4];
    const float* bd =(const float*)d_in[5];
    float* out=(float*)d_out;

    cudaFuncSetAttribute(gemm1_kernel, cudaFuncAttributeMaxDynamicSharedMemorySize, 4*S1_STAGE);
    cudaFuncSetAttribute(gemm2_kernel, cudaFuncAttributeMaxDynamicSharedMemorySize, 4*S2_STAGE);

    cvt_kernel<<<2368,256>>>((const float4*)x,(const float4*)wgu,(const float4*)wd);
    gemm1_kernel<<<dim3(45,8,NEXP),128,4*S1_STAGE>>>(rw,bgu);
    gemm2_kernel<<<dim3(36,8),128,4*S2_STAGE>>>(rw,bd,out);
}

// round 14
// speedup vs baseline: 1.7579x; 1.0090x over previous
#include <cuda_runtime.h>
#include <cuda_fp16.h>
#include <math.h>

#define TOK 1024
#define HDIM 2880
#define DDIM 2880
#define NEXP 8
#define GUCOLS 5760
#define ALPHA 1.702f
#define LIMIT 7.0f

__device__ __align__(16) __half g_wgu_h[(size_t)NEXP*HDIM*GUCOLS];
__device__ __align__(16) __half g_wd_h [(size_t)NEXP*DDIM*HDIM];
__device__ __align__(16) __half g_x_h  [(size_t)TOK*HDIM];
__device__ __align__(16) __half g_a_h  [(size_t)NEXP*TOK*DDIM];

__device__ __forceinline__ unsigned su32(const void* p){
    unsigned a; asm("{ .reg .u64 t; cvta.to.shared.u64 t, %1; cvt.u32.u64 %0, t; }":"=r"(a):"l"(p)); return a;
}
template<int N> __device__ __forceinline__ void cpwait(){
    asm volatile("cp.async.wait_group %0;"::"n"(N):"memory");
}
__device__ __forceinline__ void cpcommit(){
    asm volatile("cp.async.commit_group;":::"memory");
}
__device__ __forceinline__ void cpa16(unsigned d, const void* s){
    asm volatile("cp.async.cg.shared.global [%0], [%1], 16;"::"r"(d),"l"(s):"memory");
}
__device__ __forceinline__ void ldsm4(unsigned* r, unsigned a){
    asm volatile("ldmatrix.sync.aligned.m8n8.x4.shared.b16 {%0,%1,%2,%3}, [%4];"
        :"=r"(r[0]),"=r"(r[1]),"=r"(r[2]),"=r"(r[3]):"r"(a));
}
__device__ __forceinline__ void ldsm4t(unsigned* r, unsigned a){
    asm volatile("ldmatrix.sync.aligned.m8n8.x4.trans.shared.b16 {%0,%1,%2,%3}, [%4];"
        :"=r"(r[0]),"=r"(r[1]),"=r"(r[2]),"=r"(r[3]):"r"(a));
}
__device__ __forceinline__ void ldsm2t(unsigned* r, unsigned a){
    asm volatile("ldmatrix.sync.aligned.m8n8.x2.trans.shared.b16 {%0,%1}, [%2];"
        :"=r"(r[0]),"=r"(r[1]):"r"(a));
}
__device__ __forceinline__ void mma_fp(float* c, const unsigned* a, const unsigned* b){
    asm volatile("mma.sync.aligned.m16n8k16.row.col.f32.f16.f16.f32 "
        "{%0,%1,%2,%3},{%4,%5,%6,%7},{%8,%9},{%0,%1,%2,%3};"
        : "+f"(c[0]),"+f"(c[1]),"+f"(c[2]),"+f"(c[3])
        : "r"(a[0]),"r"(a[1]),"r"(a[2]),"r"(a[3]),"r"(b[0]),"r"(b[1]));
}

// -------- fused fp32 -> fp16 convert of x, wgu, wd (single launch) --------
#define CVT_N1 ((long long)TOK*HDIM/4)
#define CVT_N2 ((long long)NEXP*HDIM*GUCOLS/4)
#define CVT_N3 ((long long)NEXP*DDIM*HDIM/4)

__global__ void cvt_kernel(const float4* __restrict__ x, const float4* __restrict__ wgu,
                           const float4* __restrict__ wd){
    const long long NT=CVT_N1+CVT_N2+CVT_N3;
    long long i=(long long)blockIdx.x*blockDim.x+threadIdx.x, st=(long long)gridDim.x*blockDim.x;
    for(; i<NT; i+=st){
        const float4* s; uint2* d; long long j;
        if(i<CVT_N1){ s=x; d=(uint2*)g_x_h; j=i; }
        else if(i<CVT_N1+CVT_N2){ s=wgu; d=(uint2*)g_wgu_h; j=i-CVT_N1; }
        else { s=wd; d=(uint2*)g_wd_h; j=i-CVT_N1-CVT_N2; }
        float4 f=s[j];
        uint2 v;
        v.x=(unsigned)__half_as_ushort(__float2half_rn(f.x))
           |((unsigned)__half_as_ushort(__float2half_rn(f.y))<<16);
        v.y=(unsigned)__half_as_ushort(__float2half_rn(f.z))
           |((unsigned)__half_as_ushort(__float2half_rn(f.w))<<16);
        d[j]=v;
    }
}

// ======================= GEMM1: gate_up + SwiGLU ==========
// CTA tile: 128 x 128. 128 thr, 4 warps (2m x 2n of 64x64). 4 stages.
// B fragments via ldsm4t (4 per ks instead of 8 ldsm2t).
#define S1_STAGE 16384

__global__ __launch_bounds__(128,2)
void gemm1_kernel(const float* __restrict__ rw, const float* __restrict__ bgu)
{
    extern __shared__ __align__(16) char dsm[];
    __shared__ float sBias[128];
    __shared__ float sRw[128];
    const int tid=threadIdx.x, lane=tid&31, w=tid>>5;
    const int e=blockIdx.z, m0=blockIdx.y*128, c0=blockIdx.x*128, dbase=blockIdx.x*64;
    const unsigned db=su32(dsm);
    sBias[tid]=bgu[(size_t)e*GUCOLS+c0+tid];
    sRw[tid]=rw[(size_t)(m0+tid)*NEXP+e];

    const __half* xh = g_x_h + (size_t)m0*HDIM;
    const __half* wh = g_wgu_h + (size_t)e*HDIM*GUCOLS + c0;

    unsigned aoffv[4], boffv[4];
    unsigned asrc[4];
    unsigned bsrc_r[4], bsrc_c[4];
    #pragma unroll
    for(int i=0;i<4;i++){
        int li=tid+128*i;
        int ar=li>>2, ac=li&3;
        aoffv[i]=(unsigned)ar*64 + (unsigned)((ac ^ ((ar>>1)&3))*16);
        asrc[i]=(unsigned)ar*HDIM + ac*8;
        int br2=li>>4, bc2=li&15;
        boffv[i]=8192u + (unsigned)br2*256 + (unsigned)((bc2 ^ (br2&7))*16);
        bsrc_r[i]=(unsigned)br2; bsrc_c[i]=(unsigned)bc2*8;
    }

    const int NCH=HDIM/32; // 90
    auto LOAD=[&](int kc){
        if(kc<NCH){
            const unsigned st=db+(unsigned)(kc&3)*S1_STAGE;
            const int k0=kc*32;
            #pragma unroll
            for(int i=0;i<4;i++)
                cpa16(st+aoffv[i], xh+asrc[i]+k0);
            #pragma unroll
            for(int i=0;i<4;i++)
                cpa16(st+boffv[i], wh+(size_t)(k0+bsrc_r[i])*GUCOLS+bsrc_c[i]);
        }
        cpcommit();
    };

    const int mw=(w&1)*64, nw=(w>>1)*64;
    float C[4][8][4];
    #pragma unroll
    for(int i=0;i<4;i++)
        #pragma unroll
        for(int j=0;j<8;j++)
            #pragma unroll
            for(int q=0;q<4;q++) C[i][j][q]=0.f;

    const int rl=lane&15;
    const unsigned aswz=((rl>>1)&3);
    const unsigned bswz=(lane&7);

    LOAD(0); LOAD(1); LOAD(2);
    for(int kc=0;kc<NCH;kc++){
        if(kc==NCH-1) cpwait<0>(); else cpwait<2>();
        __syncthreads();
        LOAD(kc+3);
        const unsigned ab=db+(unsigned)(kc&3)*S1_STAGE;
        const unsigned bb=ab+8192;
        #pragma unroll
        for(int ks=0;ks<2;ks++){
            unsigned a[4][4],b_h[8][2];
            const unsigned boff=bb+(unsigned)(ks*16+rl)*256;
            #pragma unroll
            for(int p=0;p<4;p++){
                unsigned r4[4];
                ldsm4t(r4, boff+((((nw>>3)+2*p+(lane>>4))^bswz)*16));
                b_h[2*p][0]=r4[0];   b_h[2*p][1]=r4[1];
                b_h[2*p+1][0]=r4[2]; b_h[2*p+1][1]=r4[3];
            }
            const unsigned aoff=ab+(unsigned)(mw+rl)*64+((((lane>>4)+ks*2)^aswz)*16);
            #pragma unroll
            for(int mt=0;mt<4;mt++) ldsm4(a[mt],aoff+mt*1024);
            #pragma unroll
            for(int mt=0;mt<4;mt++)
                #pragma unroll
                for(int nt=0;nt<8;nt++)
                    mma_fp(C[mt][nt],a[mt],b_h[nt]);
        }
    }
    __syncthreads();

    float* sv=(float*)dsm;
    const int grp=lane>>2, tq=lane&3;
    #pragma unroll
    for(int mt=0;mt<4;mt++)
        #pragma unroll
        for(int nt=0;nt<8;nt++){
            const int colL=nw+nt*8+tq*2;
            const int d=(nw>>1)+nt*4+tq;
            #pragma unroll
            for(int h=0;h<2;h++){
                const int row=mw+mt*16+grp+h*8;
                float g=C[mt][nt][2*h]  +sBias[colL];
                float u=C[mt][nt][2*h+1]+sBias[colL+1];
                g=fminf(g,LIMIT);
                u=fminf(fmaxf(u,-LIMIT),LIMIT);
                float glu=g/(1.0f+__expf(-ALPHA*g));
                sv[row*68+d]=(u+1.0f)*glu*sRw[row];
            }
        }
    __syncthreads();
    {
        const int row=tid;
        __half* oh=g_a_h+((size_t)e*TOK+m0+row)*DDIM+dbase;
        #pragma unroll
        for(int j=0;j<64;j+=8){
            unsigned hv[4];
            #pragma unroll
            for(int q=0;q<4;q++){
                float aa=sv[row*68+j+2*q], b=sv[row*68+j+2*q+1];
                hv[q]=(unsigned)__half_as_ushort(__float2half_rn(aa))
                     |((unsigned)__half_as_ushort(__float2half_rn(b))<<16);
            }
            *(uint4*)(oh+j)=make_uint4(hv[0],hv[1],hv[2],hv[3]);
        }
    }
}

// ======================= GEMM2: down proj + bias + expert sum =======================
// CTA tile: 128 tokens x 80 h (288 CTAs). 128 thr, 4 warps (2m x 2n of 64x40).
// B fragments: 2x ldsm4t + 1x ldsm2t per ks.
#define S2_BHI 8192
#define S2_STAGE 13824

__global__ __launch_bounds__(128,2)
void gemm2_kernel(const float* __restrict__ rw, const float* __restrict__ bd,
                  float* __restrict__ out)
{
    extern __shared__ __align__(16) char dsm[];
    __shared__ float sRw[128*8];
    __shared__ float sBd[8*80];
    const int tid=threadIdx.x, lane=tid&31, w=tid>>5;
    const int m0=blockIdx.y*128, h0=blockIdx.x*80;
    const unsigned db=su32(dsm);
    for(int i=tid;i<1024;i+=128) sRw[i]=rw[(size_t)(m0+(i>>3))*NEXP+(i&7)];
    for(int i=tid;i<640;i+=128) sBd[i]=bd[(size_t)(i/80)*HDIM+h0+(i%80)];

    unsigned aoffv[4], asrc[4];
    #pragma unroll
    for(int i=0;i<4;i++){
        int li=tid+128*i;
        int ar=li>>2, ac=li&3;
        aoffv[i]=(unsigned)ar*64 + (unsigned)((ac ^ ((ar>>1)&3))*16);
        asrc[i]=(unsigned)ar*DDIM + ac*8;
    }

    const int NCH=NEXP*90; // 720
    auto LOAD=[&](int kc){
        if(kc<NCH){
            const int e=kc/90, kl=(kc-e*90)*32;
            const unsigned st=db+(unsigned)(kc&3)*S2_STAGE;
            const __half* ah=g_a_h+((size_t)e*TOK+m0)*DDIM+kl;
            #pragma unroll
            for(int i=0;i<4;i++)
                cpa16(st+aoffv[i], ah+asrc[i]);
            const __half* bh=g_wd_h+((size_t)e*DDIM+kl)*HDIM+h0;
            #pragma unroll
            for(int i=0;i<3;i++){
                int ch=tid+128*i;      // 0..383, need 320
                if(ch<320){
                    int r=ch/10, c=ch-r*10;
                    cpa16(st+S2_BHI+r*176+c*16, bh+(size_t)r*HDIM+c*8);
                }
            }
        }
        cpcommit();
    };

    const int mw=(w&1)*64, nw=(w>>1)*40;
    float C[4][5][4];
    #pragma unroll
    for(int i=0;i<4;i++)
        #pragma unroll
        for(int j=0;j<5;j++)
            #pragma unroll
            for(int q=0;q<4;q++) C[i][j][q]=0.f;

    const int rl=lane&15;
    const unsigned aswz=((rl>>1)&3);

    LOAD(0); LOAD(1); LOAD(2);
    for(int kc=0;kc<NCH;kc++){
        if(kc==NCH-1) cpwait<0>(); else cpwait<2>();
        __syncthreads();
        LOAD(kc+3);
        const unsigned ab=db+(unsigned)(kc&3)*S2_STAGE;
        #pragma unroll
        for(int ks=0;ks<2;ks++){
            unsigned a[4][4],b_h[5][2];
            const unsigned bbase=ab+S2_BHI+(unsigned)(ks*16+rl)*176;
            #pragma unroll
            for(int p=0;p<2;p++){
                unsigned r4[4];
                ldsm4t(r4, bbase+(unsigned)(nw+(2*p+(lane>>4))*8)*2);
                b_h[2*p][0]=r4[0];   b_h[2*p][1]=r4[1];
                b_h[2*p+1][0]=r4[2]; b_h[2*p+1][1]=r4[3];
            }
            ldsm2t(b_h[4],bbase+(unsigned)(nw+4*8)*2);
            const unsigned aoff=ab+(unsigned)(mw+rl)*64+((((lane>>4)+ks*2)^aswz)*16);
            #pragma unroll
            for(int mt=0;mt<4;mt++) ldsm4(a[mt],aoff+mt*1024);
            #pragma unroll
            for(int mt=0;mt<4;mt++)
                #pragma unroll
                for(int nt=0;nt<5;nt++)
                    mma_fp(C[mt][nt],a[mt],b_h[nt]);
        }
    }

    // epilogue: + sum_e rw*bd (smem), write fp32 out
    const int grp=lane>>2, tq=lane&3;
    #pragma unroll
    for(int nt=0;nt<5;nt++){
        const int colL=nw+nt*8+tq*2;
        const int col=h0+colL;
        #pragma unroll
        for(int mt=0;mt<4;mt++)
            #pragma unroll
            for(int h=0;h<2;h++){
                const int row=mw+mt*16+grp+h*8;
                float v0=C[mt][nt][2*h], v1=C[mt][nt][2*h+1];
                #pragma unroll
                for(int e2=0;e2<NEXP;e2++){
                    float r=sRw[row*8+e2];
                    v0=fmaf(r,sBd[e2*80+colL],v0);
                    v1=fmaf(r,sBd[e2*80+colL+1],v1);
                }
                float2 t; t.x=v0; t.y=v1;
                *(float2*)(out+(size_t)(m0+row)*HDIM+col)=t;
            }
    }
}

extern "C" void kernel_launch(void* const* d_in, const int* in_sizes, int n_in,
                              void* d_out, int out_size)
{
    const float* x  =(const float*)d_in[0];
    const float* rw =(const float*)d_in[1];
    const float* wgu=(const float*)d_in[2];
    const float* bgu=(const float*)d_in[3];
    const float* wd =(const float*)d_in[4];
    const float* bd =(const float*)d_in[5];
    float* out=(float*)d_out;

    cudaFuncSetAttribute(gemm1_kernel, cudaFuncAttributeMaxDynamicSharedMemorySize, 4*S1_STAGE);
    cudaFuncSetAttribute(gemm2_kernel, cudaFuncAttributeMaxDynamicSharedMemorySize, 4*S2_STAGE);

    cvt_kernel<<<2368,256>>>((const float4*)x,(const float4*)wgu,(const float4*)wd);
    gemm1_kernel<<<dim3(45,8,NEXP),128,4*S1_STAGE>>>(rw,bgu);
    gemm2_kernel<<<dim3(36,8),128,4*S2_STAGE>>>(rw,bd,out);
}